// round 13
// baseline (speedup 1.0000x reference)
#include <cuda_runtime.h>
#include <cuda.h>
#include <cuda_fp16.h>
#include <cstdint>

// Shapes: X [8192,4096] fp32, W [4096,4096], b[4096], out [8192,4096] fp32.
static const int MTOT = 8192;
static const int NTOT = 4096;
static const int KTOT = 4096;

#define BM 128
#define BN 128
#define BK 64
#define SSTAGE 32768        // Xh 16K + Wh 16K
#define NSTAGES 3
#define SMEM_DATA_OFF 1024
#define NCHUNK (KTOT / BK)  // 64

// Scratch (__device__ globals; allocation-free rule)
__device__ __align__(1024) __half g_Xh[(size_t)MTOT * KTOT];
__device__ __align__(1024) __half g_Wh[(size_t)NTOT * KTOT];

// ---------------------------------------------------------------------------
// PTX helpers (sm_90 base-target features only)
// ---------------------------------------------------------------------------
__device__ __forceinline__ void ldsm4(uint32_t& r0, uint32_t& r1, uint32_t& r2,
                                      uint32_t& r3, uint32_t addr) {
    asm volatile("ldmatrix.sync.aligned.m8n8.x4.shared.b16 {%0,%1,%2,%3}, [%4];"
                 : "=r"(r0), "=r"(r1), "=r"(r2), "=r"(r3) : "r"(addr));
}
__device__ __forceinline__ void mma16816(float* c, const uint32_t* a,
                                         uint32_t b0, uint32_t b1) {
    asm volatile(
        "mma.sync.aligned.m16n8k16.row.col.f32.f16.f16.f32 "
        "{%0,%1,%2,%3},{%4,%5,%6,%7},{%8,%9},{%0,%1,%2,%3};"
        : "+f"(c[0]), "+f"(c[1]), "+f"(c[2]), "+f"(c[3])
        : "r"(a[0]), "r"(a[1]), "r"(a[2]), "r"(a[3]), "r"(b0), "r"(b1));
}
__device__ __forceinline__ void tma2d(uint32_t dst, const void* map, int x, int y,
                                      uint32_t mbar) {
    asm volatile(
        "cp.async.bulk.tensor.2d.shared::cta.global.tile.mbarrier::complete_tx::bytes "
        "[%0], [%1, {%2, %3}], [%4];"
        :: "r"(dst), "l"(map), "r"(x), "r"(y), "r"(mbar) : "memory");
}
#define MBAR_INIT(a, c) \
    asm volatile("mbarrier.init.shared.b64 [%0], %1;" :: "r"(a), "r"(c) : "memory")
#define MBAR_EXPECT_TX(a, b) \
    asm volatile("mbarrier.arrive.expect_tx.shared.b64 _, [%0], %1;" :: "r"(a), "r"(b) : "memory")
#define MBAR_WAIT(a, ph) do {                                                    \
    asm volatile("{\n .reg .pred P;\n"                                           \
        "WL_%=: mbarrier.try_wait.parity.acquire.cta.shared::cta.b64 P, [%0], %1;\n" \
        "@P bra WD_%=;\n bra WL_%=;\n WD_%=:\n}"                                 \
        :: "r"(a), "r"(ph) : "memory"); } while (0)

// ---------------------------------------------------------------------------
// Fused prep kernel (256 threads). Grid = 9*1024 blocks:
//   blockIdx.x % 9 == 8  -> build_w tile (1024 blocks, inline-packed factors)
//   else                 -> split_x slice (8192 blocks, 1024 float4 each)
// Interleaved roles co-schedule both memory streams in every wave.
// ---------------------------------------------------------------------------
__global__ void __launch_bounds__(256)
prep_kernel(const float4* __restrict__ x,
            const float* __restrict__ W,
            const float* __restrict__ A_u,
            const float* __restrict__ B_u,
            const float* __restrict__ A0,
            const float* __restrict__ B0) {
    __shared__ __align__(1024) char smem[32768];  // Bc 16K | AcT 16K
    int tid = threadIdx.x;
    int g = blockIdx.x / 9, r9 = blockIdx.x % 9;

    if (r9 != 8) {
        // ---- split_x: convert 1024 float4 (4096 floats) to fp16 ----
        int base = (g * 8 + r9) * 1024 + tid;
        float4 v[4];
#pragma unroll
        for (int j = 0; j < 4; j++) v[j] = x[base + j * 256];
#pragma unroll
        for (int j = 0; j < 4; j++) {
            ushort4 h;
            h.x = __half_as_ushort(__float2half_rn(v[j].x));
            h.y = __half_as_ushort(__float2half_rn(v[j].y));
            h.z = __half_as_ushort(__float2half_rn(v[j].z));
            h.w = __half_as_ushort(__float2half_rn(v[j].w));
            reinterpret_cast<ushort4*>(g_Xh)[base + j * 256] = h;
        }
        return;
    }

    // ---- build_w tile: W_eff[128n x 128k] = W + B_cat @ A_cat ----
    int bn = g >> 5;   // 0..31 (n tile)
    int bk = g & 31;   // 0..31 (k tile)
    uint32_t sbase = (uint32_t)__cvta_generic_to_shared(smem);
    int nb = bn * 128, kb = bk * 128;

    // Fill B_cat tile [128 n-rows x 64 u] into sbase (swizzled), and
    // A_catT tile [128 k-rows x 64 u] into sbase+16384, packing inline:
    //   A_cat^T[k,u]: u<8 -> A_u[u,k]; else r=u-8,
    //                 A0[((r - k/2048)%56+56)%56, k%2048]
    //   B_cat[n,u]:   u<8 -> B_u[n,u]; else r=u-8,
    //                 B0[n%2048, ((r - n/2048)%56+56)%56]
    for (int idx = tid; idx < 8192; idx += 256) {
        int rr = idx >> 6, u = idx & 63;
        int n = nb + rr, k = kb + rr;
        float bv, av;
        if (u < 8) {
            bv = B_u[n * 8 + u];
            av = A_u[u * 4096 + k];
        } else {
            int r = u - 8;
            int ib = ((r - (n >> 11)) % 56 + 56) % 56;
            bv = B0[(n & 2047) * 56 + ib];
            int ia = ((r - (k >> 11)) % 56 + 56) % 56;
            av = A0[ia * 2048 + (k & 2047)];
        }
        uint32_t off = rr * 128 + ((((u >> 3) ^ (rr & 7))) << 4) + (u & 7) * 2;
        *reinterpret_cast<__half*>(smem + off) = __float2half_rn(bv);
        *reinterpret_cast<__half*>(smem + 16384 + off) = __float2half_rn(av);
    }
    __syncthreads();

    if (tid >= 128) return;  // MMA half only (no further barriers)

    int lane = tid & 31, warp = tid >> 5;
    int wm = warp >> 1;   // n half
    int wn = warp & 1;    // k half

    float acc[4][8][4];
#pragma unroll
    for (int a = 0; a < 4; a++)
#pragma unroll
        for (int b = 0; b < 8; b++)
#pragma unroll
            for (int c = 0; c < 4; c++) acc[a][b][c] = 0.0f;

    int arow = wm * 64 + (lane & 15);
    int nrow0 = wn * 64 + (lane & 7) + ((lane >> 4) << 3);

#pragma unroll
    for (int ks = 0; ks < 4; ks++) {
        uint32_t ah[4][4], bh[4][4];
        int ach = ks * 2 + (lane >> 4);
        int bch = ks * 2 + ((lane >> 3) & 1);
#pragma unroll
        for (int mt = 0; mt < 4; mt++) {
            int row = arow + mt * 16;
            uint32_t off = row * 128 + ((ach ^ (row & 7)) << 4);
            ldsm4(ah[mt][0], ah[mt][1], ah[mt][2], ah[mt][3], sbase + off);
        }
#pragma unroll
        for (int q = 0; q < 4; q++) {
            int row = nrow0 + q * 16;
            uint32_t off = row * 128 + ((bch ^ (row & 7)) << 4);
            ldsm4(bh[q][0], bh[q][1], bh[q][2], bh[q][3], sbase + 16384 + off);
        }
#pragma unroll
        for (int mt = 0; mt < 4; mt++) {
#pragma unroll
            for (int nt = 0; nt < 8; nt++) {
                int q = nt >> 1, o = (nt & 1) * 2;
                mma16816(acc[mt][nt], ah[mt], bh[q][o], bh[q][o + 1]);
            }
        }
    }

    // Epilogue: Wh[n,k] = fp16(W[n,k] + delta)
    int gid = lane >> 2, tig = lane & 3;
    int nb2 = nb + wm * 64;
    int kb2 = kb + wn * 64;
#pragma unroll
    for (int nt = 0; nt < 8; nt++) {
        int c = kb2 + nt * 8 + tig * 2;
#pragma unroll
        for (int mt = 0; mt < 4; mt++) {
            int r0 = nb2 + mt * 16 + gid;
            int r1 = r0 + 8;
            float2 w0 = *reinterpret_cast<const float2*>(W + (size_t)r0 * 4096 + c);
            float2 w1 = *reinterpret_cast<const float2*>(W + (size_t)r1 * 4096 + c);
            __half2 h0 = __floats2half2_rn(w0.x + acc[mt][nt][0],
                                           w0.y + acc[mt][nt][1]);
            __half2 h1 = __floats2half2_rn(w1.x + acc[mt][nt][2],
                                           w1.y + acc[mt][nt][3]);
            *reinterpret_cast<__half2*>(g_Wh + (size_t)r0 * 4096 + c) = h0;
            *reinterpret_cast<__half2*>(g_Wh + (size_t)r1 * 4096 + c) = h1;
        }
    }
}

// ---------------------------------------------------------------------------
// GEMM  out = Xh * Wh^T + b   (fp16 inputs, fp32 accum)  — R11 version.
// CTA 128x128xBK64, 128 threads (4 warps, 2x2), warp tile 64x64,
// TMA-fed 3-stage mbarrier pipeline, 2 CTAs/SM, reg double-buffered ks loop.
// ---------------------------------------------------------------------------
__global__ void __launch_bounds__(128, 2)
gemm_kernel(const __grid_constant__ CUtensorMap mXh,
            const __grid_constant__ CUtensorMap mWh,
            const float* __restrict__ bias, float* __restrict__ out) {
    extern __shared__ char smem[];
    uint32_t sbase = (uint32_t)__cvta_generic_to_shared(smem);
    int tid = threadIdx.x;
    int lane = tid & 31, warp = tid >> 5;
    int wm = warp >> 1;
    int wn = warp & 1;
    int bm = blockIdx.y, bn = blockIdx.x;

    uint32_t full[NSTAGES] = {sbase, sbase + 8, sbase + 16};

    if (tid == 0) {
        MBAR_INIT(full[0], 1);
        MBAR_INIT(full[1], 1);
        MBAR_INIT(full[2], 1);
    }
    __syncthreads();

    auto issue_stage = [&](int s, int kt) {
        uint32_t st = sbase + SMEM_DATA_OFF + s * SSTAGE;
        MBAR_EXPECT_TX(full[s], SSTAGE);
        tma2d(st,         &mXh, kt * BK, bm * BM, full[s]);
        tma2d(st + 16384, &mWh, kt * BK, bn * BN, full[s]);
    };

    if (tid == 0) {
        issue_stage(0, 0);
        issue_stage(1, 1);
    }

    float acc[4][8][4];
#pragma unroll
    for (int a = 0; a < 4; a++)
#pragma unroll
        for (int b = 0; b < 8; b++)
#pragma unroll
            for (int c = 0; c < 4; c++) acc[a][b][c] = 0.0f;

    int arow = wm * 64 + (lane & 15);
    int nrow0 = wn * 64 + (lane & 7) + ((lane >> 4) << 3);

    uint32_t ah[2][4][4];
    uint32_t bh[2][4][4];
    int ph[NSTAGES] = {0, 0, 0};

    for (int kt = 0; kt < NCHUNK; kt++) {
        int cs = kt % NSTAGES;
        __syncthreads();
        if (tid == 0 && kt + 2 < NCHUNK) issue_stage((kt + 2) % NSTAGES, kt + 2);
        MBAR_WAIT(full[cs], ph[cs]);
        ph[cs] ^= 1;

        uint32_t st = sbase + SMEM_DATA_OFF + cs * SSTAGE;

        auto ldfrag = [&](int buf, int ks) {
            int ach = ks * 2 + (lane >> 4);
            int bch = ks * 2 + ((lane >> 3) & 1);
#pragma unroll
            for (int mt = 0; mt < 4; mt++) {
                int row = arow + mt * 16;
                uint32_t off = row * 128 + ((ach ^ (row & 7)) << 4);
                ldsm4(ah[buf][mt][0], ah[buf][mt][1], ah[buf][mt][2],
                      ah[buf][mt][3], st + off);
            }
#pragma unroll
            for (int q = 0; q < 4; q++) {
                int row = nrow0 + q * 16;
                uint32_t off = row * 128 + ((bch ^ (row & 7)) << 4);
                ldsm4(bh[buf][q][0], bh[buf][q][1], bh[buf][q][2],
                      bh[buf][q][3], st + 16384 + off);
            }
        };

        ldfrag(0, 0);
#pragma unroll
        for (int ks = 0; ks < 4; ks++) {
            int cur = ks & 1, nxt = cur ^ 1;
            if (ks < 3) ldfrag(nxt, ks + 1);
#pragma unroll
            for (int mt = 0; mt < 4; mt++) {
#pragma unroll
                for (int nt = 0; nt < 8; nt++) {
                    int q = nt >> 1, o = (nt & 1) * 2;
                    mma16816(acc[mt][nt], ah[cur][mt], bh[cur][q][o],
                             bh[cur][q][o + 1]);
                }
            }
        }
    }

    const float* bptr = bias + bn * BN + wn * 64;
    size_t outbase = (size_t)(bm * BM + wm * 64) * 4096 + bn * BN + wn * 64;
    int gid = lane >> 2, tig = lane & 3;
#pragma unroll
    for (int nt = 0; nt < 8; nt++) {
        int c = nt * 8 + tig * 2;
        float b0 = bptr[c], b1 = bptr[c + 1];
#pragma unroll
        for (int mt = 0; mt < 4; mt++) {
            int r = mt * 16 + gid;
            float2 v0 = make_float2(acc[mt][nt][0] + b0, acc[mt][nt][1] + b1);
            float2 v1 = make_float2(acc[mt][nt][2] + b0, acc[mt][nt][3] + b1);
            *reinterpret_cast<float2*>(out + outbase + (size_t)r * 4096 + c) = v0;
            *reinterpret_cast<float2*>(out + outbase + (size_t)(r + 8) * 4096 + c) = v1;
        }
    }
}

// ---------------------------------------------------------------------------
typedef CUresult (*EncodeFn)(CUtensorMap*, CUtensorMapDataType, cuuint32_t, void*,
                             const cuuint64_t*, const cuuint64_t*, const cuuint32_t*,
                             const cuuint32_t*, CUtensorMapInterleave, CUtensorMapSwizzle,
                             CUtensorMapL2promotion, CUtensorMapFloatOOBfill);

static void make_map(EncodeFn enc, CUtensorMap* m, void* ptr, uint64_t rows) {
    cuuint64_t dims[2] = {(cuuint64_t)KTOT, (cuuint64_t)rows};
    cuuint64_t strides[1] = {(cuuint64_t)KTOT * 2};
    cuuint32_t box[2] = {BK, BM};
    cuuint32_t es[2] = {1, 1};
    enc(m, CU_TENSOR_MAP_DATA_TYPE_BFLOAT16, 2, ptr, dims, strides, box, es,
        CU_TENSOR_MAP_INTERLEAVE_NONE, CU_TENSOR_MAP_SWIZZLE_128B,
        CU_TENSOR_MAP_L2_PROMOTION_L2_128B, CU_TENSOR_MAP_FLOAT_OOB_FILL_NONE);
}

extern "C" void kernel_launch(void* const* d_in, const int* in_sizes, int n_in,
                              void* d_out, int out_size) {
    const float* x  = (const float*)d_in[0];
    const float* W  = (const float*)d_in[1];
    const float* b  = (const float*)d_in[2];
    const float* Au = (const float*)d_in[3];
    const float* Bu = (const float*)d_in[4];
    const float* A0 = (const float*)d_in[5];
    const float* B0 = (const float*)d_in[6];
    float* out = (float*)d_out;

    void* fp = nullptr;
    cudaDriverEntryPointQueryResult qr;
    cudaGetDriverEntryPoint("cuTensorMapEncodeTiled", &fp, cudaEnableDefault, &qr);
    EncodeFn enc = (EncodeFn)fp;

    void *pXh, *pWh;
    cudaGetSymbolAddress(&pXh, g_Xh);
    cudaGetSymbolAddress(&pWh, g_Wh);
    CUtensorMap mXh, mWh;
    make_map(enc, &mXh, pXh, MTOT);
    make_map(enc, &mWh, pWh, NTOT);

    // Fused prep: 8192 split_x blocks + 1024 build_w blocks, interleaved 8:1.
    prep_kernel<<<9 * 1024, 256>>>((const float4*)x, W, Au, Bu, A0, B0);

    int dsmem = SMEM_DATA_OFF + NSTAGES * SSTAGE;
    cudaFuncSetAttribute(gemm_kernel,
                         cudaFuncAttributeMaxDynamicSharedMemorySize, dsmem);
    gemm_kernel<<<dim3(NTOT / BN, MTOT / BM), 128, dsmem>>>(mXh, mWh, b, out);
}

// round 14
// speedup vs baseline: 1.0282x; 1.0282x over previous
#include <cuda_runtime.h>
#include <cuda.h>
#include <cuda_fp16.h>
#include <cstdint>

// Shapes: X [8192,4096] fp32, W [4096,4096], b[4096], out [8192,4096] fp32.
static const int MTOT = 8192;
static const int NTOT = 4096;
static const int KTOT = 4096;

#define BM 128
#define BN 128
#define BK 64
#define SSTAGE 32768        // Xh 16K + Wh 16K
#define NSTAGES 3
#define SMEM_DATA_OFF 1024
#define NCHUNK (KTOT / BK)  // 64

// Scratch (__device__ globals; allocation-free rule)
__device__ __align__(1024) __half g_Xh[(size_t)MTOT * KTOT];
__device__ __align__(1024) __half g_Wh[(size_t)NTOT * KTOT];

// ---------------------------------------------------------------------------
// PTX helpers (sm_90 base-target features only)
// ---------------------------------------------------------------------------
__device__ __forceinline__ void ldsm4(uint32_t& r0, uint32_t& r1, uint32_t& r2,
                                      uint32_t& r3, uint32_t addr) {
    asm volatile("ldmatrix.sync.aligned.m8n8.x4.shared.b16 {%0,%1,%2,%3}, [%4];"
                 : "=r"(r0), "=r"(r1), "=r"(r2), "=r"(r3) : "r"(addr));
}
__device__ __forceinline__ void mma16816(float* c, const uint32_t* a,
                                         uint32_t b0, uint32_t b1) {
    asm volatile(
        "mma.sync.aligned.m16n8k16.row.col.f32.f16.f16.f32 "
        "{%0,%1,%2,%3},{%4,%5,%6,%7},{%8,%9},{%0,%1,%2,%3};"
        : "+f"(c[0]), "+f"(c[1]), "+f"(c[2]), "+f"(c[3])
        : "r"(a[0]), "r"(a[1]), "r"(a[2]), "r"(a[3]), "r"(b0), "r"(b1));
}
__device__ __forceinline__ void tma2d(uint32_t dst, const void* map, int x, int y,
                                      uint32_t mbar) {
    asm volatile(
        "cp.async.bulk.tensor.2d.shared::cta.global.tile.mbarrier::complete_tx::bytes "
        "[%0], [%1, {%2, %3}], [%4];"
        :: "r"(dst), "l"(map), "r"(x), "r"(y), "r"(mbar) : "memory");
}
#define MBAR_INIT(a, c) \
    asm volatile("mbarrier.init.shared.b64 [%0], %1;" :: "r"(a), "r"(c) : "memory")
#define MBAR_EXPECT_TX(a, b) \
    asm volatile("mbarrier.arrive.expect_tx.shared.b64 _, [%0], %1;" :: "r"(a), "r"(b) : "memory")
#define MBAR_WAIT(a, ph) do {                                                    \
    asm volatile("{\n .reg .pred P;\n"                                           \
        "WL_%=: mbarrier.try_wait.parity.acquire.cta.shared::cta.b64 P, [%0], %1;\n" \
        "@P bra WD_%=;\n bra WL_%=;\n WD_%=:\n}"                                 \
        :: "r"(a), "r"(ph) : "memory"); } while (0)

// ---------------------------------------------------------------------------
// Kernel 1: convert X to fp16 (2 independent float4s per thread for MLP)
// ---------------------------------------------------------------------------
__global__ void split_x_kernel(const float4* __restrict__ x, int n4) {
    int i = blockIdx.x * blockDim.x + threadIdx.x;
    int j = i + (n4 >> 1);
    float4 v0 = x[i];
    float4 v1 = x[j];
    ushort4 h0, h1;
    h0.x = __half_as_ushort(__float2half_rn(v0.x));
    h0.y = __half_as_ushort(__float2half_rn(v0.y));
    h0.z = __half_as_ushort(__float2half_rn(v0.z));
    h0.w = __half_as_ushort(__float2half_rn(v0.w));
    h1.x = __half_as_ushort(__float2half_rn(v1.x));
    h1.y = __half_as_ushort(__float2half_rn(v1.y));
    h1.z = __half_as_ushort(__float2half_rn(v1.z));
    h1.w = __half_as_ushort(__float2half_rn(v1.w));
    reinterpret_cast<ushort4*>(g_Xh)[i] = h0;
    reinterpret_cast<ushort4*>(g_Xh)[j] = h1;
}

// ---------------------------------------------------------------------------
// Kernel 2: W_eff = W + B_cat @ A_cat via tensor cores, fp16 out.
// Inline packing of the rolled factors straight into swizzled smem
// (no global A_cat/B_cat round-trip, no separate pack launch).
//   A_cat^T[k,u]: u<8 -> A_u[u,k]; else r=u-8, A0[((r-k/2048)%56+56)%56, k%2048]
//   B_cat[n,u]:   u<8 -> B_u[n,u]; else r=u-8, B0[n%2048, ((r-n/2048)%56+56)%56]
// 256 threads: all fill smem, lower 128 run the 4-warp 64x64 MMA + epilogue.
// ---------------------------------------------------------------------------
__global__ void __launch_bounds__(256)
build_w_tc_kernel(const float* __restrict__ W,
                  const float* __restrict__ A_u,
                  const float* __restrict__ B_u,
                  const float* __restrict__ A0,
                  const float* __restrict__ B0) {
    __shared__ __align__(1024) char smem[32768];  // Bc 16K | AcT 16K
    uint32_t sbase = (uint32_t)__cvta_generic_to_shared(smem);
    int tid = threadIdx.x;
    int bn = blockIdx.y;
    int bk = blockIdx.x;
    int nb = bn * 128, kb = bk * 128;

    for (int idx = tid; idx < 8192; idx += 256) {
        int rr = idx >> 6, u = idx & 63;
        int n = nb + rr, k = kb + rr;
        float bv, av;
        if (u < 8) {
            bv = B_u[n * 8 + u];
            av = A_u[u * 4096 + k];
        } else {
            int r = u - 8;
            int ib = ((r - (n >> 11)) % 56 + 56) % 56;
            bv = B0[(n & 2047) * 56 + ib];
            int ia = ((r - (k >> 11)) % 56 + 56) % 56;
            av = A0[ia * 2048 + (k & 2047)];
        }
        uint32_t off = rr * 128 + ((((u >> 3) ^ (rr & 7))) << 4) + (u & 7) * 2;
        *reinterpret_cast<__half*>(smem + off) = __float2half_rn(bv);
        *reinterpret_cast<__half*>(smem + 16384 + off) = __float2half_rn(av);
    }
    __syncthreads();

    if (tid >= 128) return;  // no further barriers below

    int lane = tid & 31, warp = tid >> 5;
    int wm = warp >> 1;   // n half
    int wn = warp & 1;    // k half

    float acc[4][8][4];
#pragma unroll
    for (int a = 0; a < 4; a++)
#pragma unroll
        for (int b = 0; b < 8; b++)
#pragma unroll
            for (int c = 0; c < 4; c++) acc[a][b][c] = 0.0f;

    int arow = wm * 64 + (lane & 15);
    int nrow0 = wn * 64 + (lane & 7) + ((lane >> 4) << 3);

#pragma unroll
    for (int ks = 0; ks < 4; ks++) {
        uint32_t ah[4][4], bh[4][4];
        int ach = ks * 2 + (lane >> 4);
        int bch = ks * 2 + ((lane >> 3) & 1);
#pragma unroll
        for (int mt = 0; mt < 4; mt++) {
            int row = arow + mt * 16;
            uint32_t off = row * 128 + ((ach ^ (row & 7)) << 4);
            ldsm4(ah[mt][0], ah[mt][1], ah[mt][2], ah[mt][3], sbase + off);
        }
#pragma unroll
        for (int q = 0; q < 4; q++) {
            int row = nrow0 + q * 16;
            uint32_t off = row * 128 + ((bch ^ (row & 7)) << 4);
            ldsm4(bh[q][0], bh[q][1], bh[q][2], bh[q][3], sbase + 16384 + off);
        }
#pragma unroll
        for (int mt = 0; mt < 4; mt++) {
#pragma unroll
            for (int nt = 0; nt < 8; nt++) {
                int q = nt >> 1, o = (nt & 1) * 2;
                mma16816(acc[mt][nt], ah[mt], bh[q][o], bh[q][o + 1]);
            }
        }
    }

    // Epilogue: Wh[n,k] = fp16(W[n,k] + delta)
    int gid = lane >> 2, tig = lane & 3;
    int nb2 = nb + wm * 64;
    int kb2 = kb + wn * 64;
#pragma unroll
    for (int nt = 0; nt < 8; nt++) {
        int c = kb2 + nt * 8 + tig * 2;
#pragma unroll
        for (int mt = 0; mt < 4; mt++) {
            int r0 = nb2 + mt * 16 + gid;
            int r1 = r0 + 8;
            float2 w0 = *reinterpret_cast<const float2*>(W + (size_t)r0 * 4096 + c);
            float2 w1 = *reinterpret_cast<const float2*>(W + (size_t)r1 * 4096 + c);
            __half2 h0 = __floats2half2_rn(w0.x + acc[mt][nt][0],
                                           w0.y + acc[mt][nt][1]);
            __half2 h1 = __floats2half2_rn(w1.x + acc[mt][nt][2],
                                           w1.y + acc[mt][nt][3]);
            *reinterpret_cast<__half2*>(g_Wh + (size_t)r0 * 4096 + c) = h0;
            *reinterpret_cast<__half2*>(g_Wh + (size_t)r1 * 4096 + c) = h1;
        }
    }
}

// ---------------------------------------------------------------------------
// Kernel 3: GEMM  out = Xh * Wh^T + b  (fp16 in, fp32 acc) — R11, verbatim.
// CTA 128x128xBK64, 128 threads (4 warps, 2x2), warp tile 64x64,
// TMA-fed 3-stage mbarrier pipeline, 2 CTAs/SM, reg double-buffered ks loop.
// ---------------------------------------------------------------------------
__global__ void __launch_bounds__(128, 2)
gemm_kernel(const __grid_constant__ CUtensorMap mXh,
            const __grid_constant__ CUtensorMap mWh,
            const float* __restrict__ bias, float* __restrict__ out) {
    extern __shared__ char smem[];
    uint32_t sbase = (uint32_t)__cvta_generic_to_shared(smem);
    int tid = threadIdx.x;
    int lane = tid & 31, warp = tid >> 5;
    int wm = warp >> 1;
    int wn = warp & 1;
    int bm = blockIdx.y, bn = blockIdx.x;

    uint32_t full[NSTAGES] = {sbase, sbase + 8, sbase + 16};

    if (tid == 0) {
        MBAR_INIT(full[0], 1);
        MBAR_INIT(full[1], 1);
        MBAR_INIT(full[2], 1);
    }
    __syncthreads();

    auto issue_stage = [&](int s, int kt) {
        uint32_t st = sbase + SMEM_DATA_OFF + s * SSTAGE;
        MBAR_EXPECT_TX(full[s], SSTAGE);
        tma2d(st,         &mXh, kt * BK, bm * BM, full[s]);
        tma2d(st + 16384, &mWh, kt * BK, bn * BN, full[s]);
    };

    if (tid == 0) {
        issue_stage(0, 0);
        issue_stage(1, 1);
    }

    float acc[4][8][4];
#pragma unroll
    for (int a = 0; a < 4; a++)
#pragma unroll
        for (int b = 0; b < 8; b++)
#pragma unroll
            for (int c = 0; c < 4; c++) acc[a][b][c] = 0.0f;

    int arow = wm * 64 + (lane & 15);
    int nrow0 = wn * 64 + (lane & 7) + ((lane >> 4) << 3);

    uint32_t ah[2][4][4];
    uint32_t bh[2][4][4];
    int ph[NSTAGES] = {0, 0, 0};

    for (int kt = 0; kt < NCHUNK; kt++) {
        int cs = kt % NSTAGES;
        __syncthreads();
        if (tid == 0 && kt + 2 < NCHUNK) issue_stage((kt + 2) % NSTAGES, kt + 2);
        MBAR_WAIT(full[cs], ph[cs]);
        ph[cs] ^= 1;

        uint32_t st = sbase + SMEM_DATA_OFF + cs * SSTAGE;

        auto ldfrag = [&](int buf, int ks) {
            int ach = ks * 2 + (lane >> 4);
            int bch = ks * 2 + ((lane >> 3) & 1);
#pragma unroll
            for (int mt = 0; mt < 4; mt++) {
                int row = arow + mt * 16;
                uint32_t off = row * 128 + ((ach ^ (row & 7)) << 4);
                ldsm4(ah[buf][mt][0], ah[buf][mt][1], ah[buf][mt][2],
                      ah[buf][mt][3], st + off);
            }
#pragma unroll
            for (int q = 0; q < 4; q++) {
                int row = nrow0 + q * 16;
                uint32_t off = row * 128 + ((bch ^ (row & 7)) << 4);
                ldsm4(bh[buf][q][0], bh[buf][q][1], bh[buf][q][2],
                      bh[buf][q][3], st + 16384 + off);
            }
        };

        ldfrag(0, 0);
#pragma unroll
        for (int ks = 0; ks < 4; ks++) {
            int cur = ks & 1, nxt = cur ^ 1;
            if (ks < 3) ldfrag(nxt, ks + 1);
#pragma unroll
            for (int mt = 0; mt < 4; mt++) {
#pragma unroll
                for (int nt = 0; nt < 8; nt++) {
                    int q = nt >> 1, o = (nt & 1) * 2;
                    mma16816(acc[mt][nt], ah[cur][mt], bh[cur][q][o],
                             bh[cur][q][o + 1]);
                }
            }
        }
    }

    const float* bptr = bias + bn * BN + wn * 64;
    size_t outbase = (size_t)(bm * BM + wm * 64) * 4096 + bn * BN + wn * 64;
    int gid = lane >> 2, tig = lane & 3;
#pragma unroll
    for (int nt = 0; nt < 8; nt++) {
        int c = nt * 8 + tig * 2;
        float b0 = bptr[c], b1 = bptr[c + 1];
#pragma unroll
        for (int mt = 0; mt < 4; mt++) {
            int r = mt * 16 + gid;
            float2 v0 = make_float2(acc[mt][nt][0] + b0, acc[mt][nt][1] + b1);
            float2 v1 = make_float2(acc[mt][nt][2] + b0, acc[mt][nt][3] + b1);
            *reinterpret_cast<float2*>(out + outbase + (size_t)r * 4096 + c) = v0;
            *reinterpret_cast<float2*>(out + outbase + (size_t)(r + 8) * 4096 + c) = v1;
        }
    }
}

// ---------------------------------------------------------------------------
typedef CUresult (*EncodeFn)(CUtensorMap*, CUtensorMapDataType, cuuint32_t, void*,
                             const cuuint64_t*, const cuuint64_t*, const cuuint32_t*,
                             const cuuint32_t*, CUtensorMapInterleave, CUtensorMapSwizzle,
                             CUtensorMapL2promotion, CUtensorMapFloatOOBfill);

static void make_map(EncodeFn enc, CUtensorMap* m, void* ptr, uint64_t rows) {
    cuuint64_t dims[2] = {(cuuint64_t)KTOT, (cuuint64_t)rows};
    cuuint64_t strides[1] = {(cuuint64_t)KTOT * 2};
    cuuint32_t box[2] = {BK, BM};
    cuuint32_t es[2] = {1, 1};
    enc(m, CU_TENSOR_MAP_DATA_TYPE_BFLOAT16, 2, ptr, dims, strides, box, es,
        CU_TENSOR_MAP_INTERLEAVE_NONE, CU_TENSOR_MAP_SWIZZLE_128B,
        CU_TENSOR_MAP_L2_PROMOTION_L2_128B, CU_TENSOR_MAP_FLOAT_OOB_FILL_NONE);
}

extern "C" void kernel_launch(void* const* d_in, const int* in_sizes, int n_in,
                              void* d_out, int out_size) {
    const float* x  = (const float*)d_in[0];
    const float* W  = (const float*)d_in[1];
    const float* b  = (const float*)d_in[2];
    const float* Au = (const float*)d_in[3];
    const float* Bu = (const float*)d_in[4];
    const float* A0 = (const float*)d_in[5];
    const float* B0 = (const float*)d_in[6];
    float* out = (float*)d_out;

    void* fp = nullptr;
    cudaDriverEntryPointQueryResult qr;
    cudaGetDriverEntryPoint("cuTensorMapEncodeTiled", &fp, cudaEnableDefault, &qr);
    EncodeFn enc = (EncodeFn)fp;

    void *pXh, *pWh;
    cudaGetSymbolAddress(&pXh, g_Xh);
    cudaGetSymbolAddress(&pWh, g_Wh);
    CUtensorMap mXh, mWh;
    make_map(enc, &mXh, pXh, MTOT);
    make_map(enc, &mWh, pWh, NTOT);

    int n4 = (MTOT * KTOT) / 4;
    split_x_kernel<<<(n4 / 2 + 255) / 256, 256>>>((const float4*)x, n4);
    build_w_tc_kernel<<<dim3(KTOT / 128, NTOT / 128), 256>>>(W, Au, Bu, A0, B0);

    int dsmem = SMEM_DATA_OFF + NSTAGES * SSTAGE;
    cudaFuncSetAttribute(gemm_kernel,
                         cudaFuncAttributeMaxDynamicSharedMemorySize, dsmem);
    gemm_kernel<<<dim3(NTOT / BN, MTOT / BM), 128, dsmem>>>(mXh, mWh, b, out);
}

// round 15
// speedup vs baseline: 1.2289x; 1.1951x over previous
#include <cuda_runtime.h>
#include <cuda.h>
#include <cuda_fp16.h>
#include <cstdint>

// Shapes: X [8192,4096] fp32, W [4096,4096], b[4096], out [8192,4096] fp32.
static const int MTOT = 8192;
static const int NTOT = 4096;
static const int KTOT = 4096;

#define BM 128
#define BN 128
#define BK 64
#define SSTAGE 32768        // Xh 16K + Wh 16K
#define NSTAGES 3
#define SMEM_DATA_OFF 1024
#define NCHUNK (KTOT / BK)  // 64

// Scratch (__device__ globals; allocation-free rule)
__device__ __align__(1024) __half g_Xh[(size_t)MTOT * KTOT];
__device__ __align__(1024) __half g_Wh[(size_t)NTOT * KTOT];
__device__ __align__(1024) __half g_Bc[(size_t)NTOT * 64];   // [n, u] fp16
__device__ __align__(1024) __half g_AcT[(size_t)KTOT * 64];  // [k, u] fp16

// ---------------------------------------------------------------------------
// Kernel 1: convert X to fp16 (2 independent float4s per thread for MLP)
// ---------------------------------------------------------------------------
__global__ void split_x_kernel(const float4* __restrict__ x, int n4) {
    int i = blockIdx.x * blockDim.x + threadIdx.x;
    int j = i + (n4 >> 1);
    float4 v0 = x[i];
    float4 v1 = x[j];
    ushort4 h0, h1;
    h0.x = __half_as_ushort(__float2half_rn(v0.x));
    h0.y = __half_as_ushort(__float2half_rn(v0.y));
    h0.z = __half_as_ushort(__float2half_rn(v0.z));
    h0.w = __half_as_ushort(__float2half_rn(v0.w));
    h1.x = __half_as_ushort(__float2half_rn(v1.x));
    h1.y = __half_as_ushort(__float2half_rn(v1.y));
    h1.z = __half_as_ushort(__float2half_rn(v1.z));
    h1.w = __half_as_ushort(__float2half_rn(v1.w));
    reinterpret_cast<ushort4*>(g_Xh)[i] = h0;
    reinterpret_cast<ushort4*>(g_Xh)[j] = h1;
}

// ---------------------------------------------------------------------------
// Kernel 1b: pack low-rank factors into fp16 concat form (once, coalesced).
// ---------------------------------------------------------------------------
__global__ void pack_kernel(const float* __restrict__ A_u,
                            const float* __restrict__ B_u,
                            const float* __restrict__ A0,
                            const float* __restrict__ B0) {
    int idx = blockIdx.x * blockDim.x + threadIdx.x;
    if (idx >= KTOT * 64) return;
    int k = idx >> 6, u = idx & 63;  // n == k for the B side

    float av, bv;
    if (u < 8) {
        av = A_u[u * 4096 + k];
        bv = B_u[k * 8 + u];
    } else {
        int r = u - 8;
        int ia = ((r - (k >> 11)) % 56 + 56) % 56;
        av = A0[ia * 2048 + (k & 2047)];
        bv = B0[(k & 2047) * 56 + ia];
    }
    g_AcT[idx] = __float2half_rn(av);
    g_Bc[idx] = __float2half_rn(bv);
}

// ---------------------------------------------------------------------------
// PTX helpers (sm_90 base-target features only)
// ---------------------------------------------------------------------------
__device__ __forceinline__ void cp16(uint32_t dst, const void* src) {
    asm volatile("cp.async.cg.shared.global [%0], [%1], 16;" :: "r"(dst), "l"(src));
}
__device__ __forceinline__ void ldsm4(uint32_t& r0, uint32_t& r1, uint32_t& r2,
                                      uint32_t& r3, uint32_t addr) {
    asm volatile("ldmatrix.sync.aligned.m8n8.x4.shared.b16 {%0,%1,%2,%3}, [%4];"
                 : "=r"(r0), "=r"(r1), "=r"(r2), "=r"(r3) : "r"(addr));
}
__device__ __forceinline__ void mma16816(float* c, const uint32_t* a,
                                         uint32_t b0, uint32_t b1) {
    asm volatile(
        "mma.sync.aligned.m16n8k16.row.col.f32.f16.f16.f32 "
        "{%0,%1,%2,%3},{%4,%5,%6,%7},{%8,%9},{%0,%1,%2,%3};"
        : "+f"(c[0]), "+f"(c[1]), "+f"(c[2]), "+f"(c[3])
        : "r"(a[0]), "r"(a[1]), "r"(a[2]), "r"(a[3]), "r"(b0), "r"(b1));
}
__device__ __forceinline__ void tma2d(uint32_t dst, const void* map, int x, int y,
                                      uint32_t mbar) {
    asm volatile(
        "cp.async.bulk.tensor.2d.shared::cta.global.tile.mbarrier::complete_tx::bytes "
        "[%0], [%1, {%2, %3}], [%4];"
        :: "r"(dst), "l"(map), "r"(x), "r"(y), "r"(mbar) : "memory");
}
#define MBAR_INIT(a, c) \
    asm volatile("mbarrier.init.shared.b64 [%0], %1;" :: "r"(a), "r"(c) : "memory")
#define MBAR_EXPECT_TX(a, b) \
    asm volatile("mbarrier.arrive.expect_tx.shared.b64 _, [%0], %1;" :: "r"(a), "r"(b) : "memory")
#define MBAR_WAIT(a, ph) do {                                                    \
    asm volatile("{\n .reg .pred P;\n"                                           \
        "WL_%=: mbarrier.try_wait.parity.acquire.cta.shared::cta.b64 P, [%0], %1;\n" \
        "@P bra WD_%=;\n bra WL_%=;\n WD_%=:\n}"                                 \
        :: "r"(a), "r"(ph) : "memory"); } while (0)

// ---------------------------------------------------------------------------
// Kernel 2: W_eff = W + B_cat @ A_cat via tensor cores, store fp16 (R11).
// ---------------------------------------------------------------------------
__global__ void __launch_bounds__(128, 2)
build_w_tc_kernel(const float* __restrict__ W) {
    __shared__ __align__(1024) char smem[32768];
    uint32_t sbase = (uint32_t)__cvta_generic_to_shared(smem);
    int tid = threadIdx.x;
    int lane = tid & 31, warp = tid >> 5;
    int wm = warp >> 1;
    int wn = warp & 1;
    int bn = blockIdx.y;
    int bk = blockIdx.x;

    const __half* gB = g_Bc + (size_t)bn * 128 * 64;
    const __half* gA = g_AcT + (size_t)bk * 128 * 64;

#pragma unroll
    for (int i2 = 0; i2 < 8; i2++) {
        int idx = tid + i2 * 128;
        int r = idx >> 3, c = idx & 7;
        uint32_t dst = sbase + r * 128 + ((c ^ (r & 7)) << 4);
        cp16(dst, gB + (size_t)r * 64 + c * 8);
    }
#pragma unroll
    for (int i2 = 0; i2 < 8; i2++) {
        int idx = tid + i2 * 128;
        int r = idx >> 3, c = idx & 7;
        uint32_t dst = sbase + 16384 + r * 128 + ((c ^ (r & 7)) << 4);
        cp16(dst, gA + (size_t)r * 64 + c * 8);
    }
    asm volatile("cp.async.commit_group;");
    asm volatile("cp.async.wait_group 0;");
    __syncthreads();

    float acc[4][8][4];
#pragma unroll
    for (int a = 0; a < 4; a++)
#pragma unroll
        for (int b = 0; b < 8; b++)
#pragma unroll
            for (int c = 0; c < 4; c++) acc[a][b][c] = 0.0f;

    int arow = wm * 64 + (lane & 15);
    int nrow0 = wn * 64 + (lane & 7) + ((lane >> 4) << 3);

#pragma unroll
    for (int ks = 0; ks < 4; ks++) {
        uint32_t ah[4][4], bh[4][4];
        int ach = ks * 2 + (lane >> 4);
        int bch = ks * 2 + ((lane >> 3) & 1);
#pragma unroll
        for (int mt = 0; mt < 4; mt++) {
            int row = arow + mt * 16;
            uint32_t off = row * 128 + ((ach ^ (row & 7)) << 4);
            ldsm4(ah[mt][0], ah[mt][1], ah[mt][2], ah[mt][3], sbase + off);
        }
#pragma unroll
        for (int q = 0; q < 4; q++) {
            int row = nrow0 + q * 16;
            uint32_t off = row * 128 + ((bch ^ (row & 7)) << 4);
            ldsm4(bh[q][0], bh[q][1], bh[q][2], bh[q][3], sbase + 16384 + off);
        }
#pragma unroll
        for (int mt = 0; mt < 4; mt++) {
#pragma unroll
            for (int nt = 0; nt < 8; nt++) {
                int q = nt >> 1, o = (nt & 1) * 2;
                mma16816(acc[mt][nt], ah[mt], bh[q][o], bh[q][o + 1]);
            }
        }
    }

    int gid = lane >> 2, tig = lane & 3;
    int nb = bn * 128 + wm * 64;
    int kb = bk * 128 + wn * 64;
#pragma unroll
    for (int nt = 0; nt < 8; nt++) {
        int c = kb + nt * 8 + tig * 2;
#pragma unroll
        for (int mt = 0; mt < 4; mt++) {
            int r0 = nb + mt * 16 + gid;
            int r1 = r0 + 8;
            float2 w0 = *reinterpret_cast<const float2*>(W + (size_t)r0 * 4096 + c);
            float2 w1 = *reinterpret_cast<const float2*>(W + (size_t)r1 * 4096 + c);
            __half2 h0 = __floats2half2_rn(w0.x + acc[mt][nt][0],
                                           w0.y + acc[mt][nt][1]);
            __half2 h1 = __floats2half2_rn(w1.x + acc[mt][nt][2],
                                           w1.y + acc[mt][nt][3]);
            *reinterpret_cast<__half2*>(g_Wh + (size_t)r0 * 4096 + c) = h0;
            *reinterpret_cast<__half2*>(g_Wh + (size_t)r1 * 4096 + c) = h1;
        }
    }
}

// ---------------------------------------------------------------------------
// Kernel 3: GEMM  out = Xh * Wh^T + b  (fp16 in, fp32 acc) — R11, verbatim.
// CTA 128x128xBK64, 128 threads (4 warps, 2x2), warp tile 64x64,
// TMA-fed 3-stage mbarrier pipeline, 2 CTAs/SM, reg double-buffered ks loop.
// ---------------------------------------------------------------------------
__global__ void __launch_bounds__(128, 2)
gemm_kernel(const __grid_constant__ CUtensorMap mXh,
            const __grid_constant__ CUtensorMap mWh,
            const float* __restrict__ bias, float* __restrict__ out) {
    extern __shared__ char smem[];
    uint32_t sbase = (uint32_t)__cvta_generic_to_shared(smem);
    int tid = threadIdx.x;
    int lane = tid & 31, warp = tid >> 5;
    int wm = warp >> 1;
    int wn = warp & 1;
    int bm = blockIdx.y, bn = blockIdx.x;

    uint32_t full[NSTAGES] = {sbase, sbase + 8, sbase + 16};

    if (tid == 0) {
        MBAR_INIT(full[0], 1);
        MBAR_INIT(full[1], 1);
        MBAR_INIT(full[2], 1);
    }
    __syncthreads();

    auto issue_stage = [&](int s, int kt) {
        uint32_t st = sbase + SMEM_DATA_OFF + s * SSTAGE;
        MBAR_EXPECT_TX(full[s], SSTAGE);
        tma2d(st,         &mXh, kt * BK, bm * BM, full[s]);
        tma2d(st + 16384, &mWh, kt * BK, bn * BN, full[s]);
    };

    if (tid == 0) {
        issue_stage(0, 0);
        issue_stage(1, 1);
    }

    float acc[4][8][4];
#pragma unroll
    for (int a = 0; a < 4; a++)
#pragma unroll
        for (int b = 0; b < 8; b++)
#pragma unroll
            for (int c = 0; c < 4; c++) acc[a][b][c] = 0.0f;

    int arow = wm * 64 + (lane & 15);
    int nrow0 = wn * 64 + (lane & 7) + ((lane >> 4) << 3);

    uint32_t ah[2][4][4];
    uint32_t bh[2][4][4];
    int ph[NSTAGES] = {0, 0, 0};

    for (int kt = 0; kt < NCHUNK; kt++) {
        int cs = kt % NSTAGES;
        __syncthreads();
        if (tid == 0 && kt + 2 < NCHUNK) issue_stage((kt + 2) % NSTAGES, kt + 2);
        MBAR_WAIT(full[cs], ph[cs]);
        ph[cs] ^= 1;

        uint32_t st = sbase + SMEM_DATA_OFF + cs * SSTAGE;

        auto ldfrag = [&](int buf, int ks) {
            int ach = ks * 2 + (lane >> 4);
            int bch = ks * 2 + ((lane >> 3) & 1);
#pragma unroll
            for (int mt = 0; mt < 4; mt++) {
                int row = arow + mt * 16;
                uint32_t off = row * 128 + ((ach ^ (row & 7)) << 4);
                ldsm4(ah[buf][mt][0], ah[buf][mt][1], ah[buf][mt][2],
                      ah[buf][mt][3], st + off);
            }
#pragma unroll
            for (int q = 0; q < 4; q++) {
                int row = nrow0 + q * 16;
                uint32_t off = row * 128 + ((bch ^ (row & 7)) << 4);
                ldsm4(bh[buf][q][0], bh[buf][q][1], bh[buf][q][2],
                      bh[buf][q][3], st + 16384 + off);
            }
        };

        ldfrag(0, 0);
#pragma unroll
        for (int ks = 0; ks < 4; ks++) {
            int cur = ks & 1, nxt = cur ^ 1;
            if (ks < 3) ldfrag(nxt, ks + 1);
#pragma unroll
            for (int mt = 0; mt < 4; mt++) {
#pragma unroll
                for (int nt = 0; nt < 8; nt++) {
                    int q = nt >> 1, o = (nt & 1) * 2;
                    mma16816(acc[mt][nt], ah[cur][mt], bh[cur][q][o],
                             bh[cur][q][o + 1]);
                }
            }
        }
    }

    const float* bptr = bias + bn * BN + wn * 64;
    size_t outbase = (size_t)(bm * BM + wm * 64) * 4096 + bn * BN + wn * 64;
    int gid = lane >> 2, tig = lane & 3;
#pragma unroll
    for (int nt = 0; nt < 8; nt++) {
        int c = nt * 8 + tig * 2;
        float b0 = bptr[c], b1 = bptr[c + 1];
#pragma unroll
        for (int mt = 0; mt < 4; mt++) {
            int r = mt * 16 + gid;
            float2 v0 = make_float2(acc[mt][nt][0] + b0, acc[mt][nt][1] + b1);
            float2 v1 = make_float2(acc[mt][nt][2] + b0, acc[mt][nt][3] + b1);
            *reinterpret_cast<float2*>(out + outbase + (size_t)r * 4096 + c) = v0;
            *reinterpret_cast<float2*>(out + outbase + (size_t)(r + 8) * 4096 + c) = v1;
        }
    }
}

// ---------------------------------------------------------------------------
typedef CUresult (*EncodeFn)(CUtensorMap*, CUtensorMapDataType, cuuint32_t, void*,
                             const cuuint64_t*, const cuuint64_t*, const cuuint32_t*,
                             const cuuint32_t*, CUtensorMapInterleave, CUtensorMapSwizzle,
                             CUtensorMapL2promotion, CUtensorMapFloatOOBfill);

static void make_map(EncodeFn enc, CUtensorMap* m, void* ptr, uint64_t rows) {
    cuuint64_t dims[2] = {(cuuint64_t)KTOT, (cuuint64_t)rows};
    cuuint64_t strides[1] = {(cuuint64_t)KTOT * 2};
    cuuint32_t box[2] = {BK, BM};
    cuuint32_t es[2] = {1, 1};
    enc(m, CU_TENSOR_MAP_DATA_TYPE_BFLOAT16, 2, ptr, dims, strides, box, es,
        CU_TENSOR_MAP_INTERLEAVE_NONE, CU_TENSOR_MAP_SWIZZLE_128B,
        CU_TENSOR_MAP_L2_PROMOTION_L2_128B, CU_TENSOR_MAP_FLOAT_OOB_FILL_NONE);
}

extern "C" void kernel_launch(void* const* d_in, const int* in_sizes, int n_in,
                              void* d_out, int out_size) {
    const float* x  = (const float*)d_in[0];
    const float* W  = (const float*)d_in[1];
    const float* b  = (const float*)d_in[2];
    const float* Au = (const float*)d_in[3];
    const float* Bu = (const float*)d_in[4];
    const float* A0 = (const float*)d_in[5];
    const float* B0 = (const float*)d_in[6];
    float* out = (float*)d_out;

    void* fp = nullptr;
    cudaDriverEntryPointQueryResult qr;
    cudaGetDriverEntryPoint("cuTensorMapEncodeTiled", &fp, cudaEnableDefault, &qr);
    EncodeFn enc = (EncodeFn)fp;

    void *pXh, *pWh;
    cudaGetSymbolAddress(&pXh, g_Xh);
    cudaGetSymbolAddress(&pWh, g_Wh);
    CUtensorMap mXh, mWh;
    make_map(enc, &mXh, pXh, MTOT);
    make_map(enc, &mWh, pWh, NTOT);

    int n4 = (MTOT * KTOT) / 4;
    split_x_kernel<<<(n4 / 2 + 255) / 256, 256>>>((const float4*)x, n4);
    pack_kernel<<<(KTOT * 64 + 255) / 256, 256>>>(Au, Bu, A0, B0);
    build_w_tc_kernel<<<dim3(KTOT / 128, NTOT / 128), 128>>>(W);

    int dsmem = SMEM_DATA_OFF + NSTAGES * SSTAGE;
    cudaFuncSetAttribute(gemm_kernel,
                         cudaFuncAttributeMaxDynamicSharedMemorySize, dsmem);
    gemm_kernel<<<dim3(NTOT / BN, MTOT / BM), 128, dsmem>>>(mXh, mWh, b, out);
}

// round 16
// speedup vs baseline: 1.2544x; 1.0208x over previous
#include <cuda_runtime.h>
#include <cuda.h>
#include <cuda_fp16.h>
#include <cstdint>

// Shapes: X [8192,4096] fp32, W [4096,4096], b[4096], out [8192,4096] fp32.
static const int MTOT = 8192;
static const int NTOT = 4096;
static const int KTOT = 4096;

#define BM 128
#define BN 128
#define BK 64
#define SSTAGE 32768        // Xh 16K + Wh 16K
#define NSTAGES 3
#define SMEM_DATA_OFF 1024
#define NCHUNK (KTOT / BK)  // 64
#define NTILES ((MTOT / BM) * (NTOT / BN))  // 2048
#define GRID_PERSIST 304    // 2 CTAs/SM x 152 SMs (GB300)

// Scratch (__device__ globals; allocation-free rule)
__device__ __align__(1024) __half g_Xh[(size_t)MTOT * KTOT];
__device__ __align__(1024) __half g_Wh[(size_t)NTOT * KTOT];
__device__ __align__(1024) __half g_Bc[(size_t)NTOT * 64];   // [n, u] fp16
__device__ __align__(1024) __half g_AcT[(size_t)KTOT * 64];  // [k, u] fp16

// ---------------------------------------------------------------------------
// Kernel 1: convert X to fp16 (2 independent float4s per thread for MLP)
// ---------------------------------------------------------------------------
__global__ void split_x_kernel(const float4* __restrict__ x, int n4) {
    int i = blockIdx.x * blockDim.x + threadIdx.x;
    int j = i + (n4 >> 1);
    float4 v0 = x[i];
    float4 v1 = x[j];
    ushort4 h0, h1;
    h0.x = __half_as_ushort(__float2half_rn(v0.x));
    h0.y = __half_as_ushort(__float2half_rn(v0.y));
    h0.z = __half_as_ushort(__float2half_rn(v0.z));
    h0.w = __half_as_ushort(__float2half_rn(v0.w));
    h1.x = __half_as_ushort(__float2half_rn(v1.x));
    h1.y = __half_as_ushort(__float2half_rn(v1.y));
    h1.z = __half_as_ushort(__float2half_rn(v1.z));
    h1.w = __half_as_ushort(__float2half_rn(v1.w));
    reinterpret_cast<ushort4*>(g_Xh)[i] = h0;
    reinterpret_cast<ushort4*>(g_Xh)[j] = h1;
}

// ---------------------------------------------------------------------------
// Kernel 1b: pack low-rank factors into fp16 concat form (once, coalesced).
// ---------------------------------------------------------------------------
__global__ void pack_kernel(const float* __restrict__ A_u,
                            const float* __restrict__ B_u,
                            const float* __restrict__ A0,
                            const float* __restrict__ B0) {
    int idx = blockIdx.x * blockDim.x + threadIdx.x;
    if (idx >= KTOT * 64) return;
    int k = idx >> 6, u = idx & 63;  // n == k for the B side

    float av, bv;
    if (u < 8) {
        av = A_u[u * 4096 + k];
        bv = B_u[k * 8 + u];
    } else {
        int r = u - 8;
        int ia = ((r - (k >> 11)) % 56 + 56) % 56;
        av = A0[ia * 2048 + (k & 2047)];
        bv = B0[(k & 2047) * 56 + ia];
    }
    g_AcT[idx] = __float2half_rn(av);
    g_Bc[idx] = __float2half_rn(bv);
}

// ---------------------------------------------------------------------------
// PTX helpers (sm_90 base-target features only)
// ---------------------------------------------------------------------------
__device__ __forceinline__ void cp16(uint32_t dst, const void* src) {
    asm volatile("cp.async.cg.shared.global [%0], [%1], 16;" :: "r"(dst), "l"(src));
}
__device__ __forceinline__ void ldsm4(uint32_t& r0, uint32_t& r1, uint32_t& r2,
                                      uint32_t& r3, uint32_t addr) {
    asm volatile("ldmatrix.sync.aligned.m8n8.x4.shared.b16 {%0,%1,%2,%3}, [%4];"
                 : "=r"(r0), "=r"(r1), "=r"(r2), "=r"(r3) : "r"(addr));
}
__device__ __forceinline__ void mma16816(float* c, const uint32_t* a,
                                         uint32_t b0, uint32_t b1) {
    asm volatile(
        "mma.sync.aligned.m16n8k16.row.col.f32.f16.f16.f32 "
        "{%0,%1,%2,%3},{%4,%5,%6,%7},{%8,%9},{%0,%1,%2,%3};"
        : "+f"(c[0]), "+f"(c[1]), "+f"(c[2]), "+f"(c[3])
        : "r"(a[0]), "r"(a[1]), "r"(a[2]), "r"(a[3]), "r"(b0), "r"(b1));
}
__device__ __forceinline__ void tma2d(uint32_t dst, const void* map, int x, int y,
                                      uint32_t mbar) {
    asm volatile(
        "cp.async.bulk.tensor.2d.shared::cta.global.tile.mbarrier::complete_tx::bytes "
        "[%0], [%1, {%2, %3}], [%4];"
        :: "r"(dst), "l"(map), "r"(x), "r"(y), "r"(mbar) : "memory");
}
#define MBAR_INIT(a, c) \
    asm volatile("mbarrier.init.shared.b64 [%0], %1;" :: "r"(a), "r"(c) : "memory")
#define MBAR_EXPECT_TX(a, b) \
    asm volatile("mbarrier.arrive.expect_tx.shared.b64 _, [%0], %1;" :: "r"(a), "r"(b) : "memory")
#define MBAR_WAIT(a, ph) do {                                                    \
    asm volatile("{\n .reg .pred P;\n"                                           \
        "WL_%=: mbarrier.try_wait.parity.acquire.cta.shared::cta.b64 P, [%0], %1;\n" \
        "@P bra WD_%=;\n bra WL_%=;\n WD_%=:\n}"                                 \
        :: "r"(a), "r"(ph) : "memory"); } while (0)

// ---------------------------------------------------------------------------
// Kernel 2: W_eff = W + B_cat @ A_cat via tensor cores, store fp16 (R11).
// ---------------------------------------------------------------------------
__global__ void __launch_bounds__(128, 2)
build_w_tc_kernel(const float* __restrict__ W) {
    __shared__ __align__(1024) char smem[32768];
    uint32_t sbase = (uint32_t)__cvta_generic_to_shared(smem);
    int tid = threadIdx.x;
    int lane = tid & 31, warp = tid >> 5;
    int wm = warp >> 1;
    int wn = warp & 1;
    int bn = blockIdx.y;
    int bk = blockIdx.x;

    const __half* gB = g_Bc + (size_t)bn * 128 * 64;
    const __half* gA = g_AcT + (size_t)bk * 128 * 64;

#pragma unroll
    for (int i2 = 0; i2 < 8; i2++) {
        int idx = tid + i2 * 128;
        int r = idx >> 3, c = idx & 7;
        uint32_t dst = sbase + r * 128 + ((c ^ (r & 7)) << 4);
        cp16(dst, gB + (size_t)r * 64 + c * 8);
    }
#pragma unroll
    for (int i2 = 0; i2 < 8; i2++) {
        int idx = tid + i2 * 128;
        int r = idx >> 3, c = idx & 7;
        uint32_t dst = sbase + 16384 + r * 128 + ((c ^ (r & 7)) << 4);
        cp16(dst, gA + (size_t)r * 64 + c * 8);
    }
    asm volatile("cp.async.commit_group;");
    asm volatile("cp.async.wait_group 0;");
    __syncthreads();

    float acc[4][8][4];
#pragma unroll
    for (int a = 0; a < 4; a++)
#pragma unroll
        for (int b = 0; b < 8; b++)
#pragma unroll
            for (int c = 0; c < 4; c++) acc[a][b][c] = 0.0f;

    int arow = wm * 64 + (lane & 15);
    int nrow0 = wn * 64 + (lane & 7) + ((lane >> 4) << 3);

#pragma unroll
    for (int ks = 0; ks < 4; ks++) {
        uint32_t ah[4][4], bh[4][4];
        int ach = ks * 2 + (lane >> 4);
        int bch = ks * 2 + ((lane >> 3) & 1);
#pragma unroll
        for (int mt = 0; mt < 4; mt++) {
            int row = arow + mt * 16;
            uint32_t off = row * 128 + ((ach ^ (row & 7)) << 4);
            ldsm4(ah[mt][0], ah[mt][1], ah[mt][2], ah[mt][3], sbase + off);
        }
#pragma unroll
        for (int q = 0; q < 4; q++) {
            int row = nrow0 + q * 16;
            uint32_t off = row * 128 + ((bch ^ (row & 7)) << 4);
            ldsm4(bh[q][0], bh[q][1], bh[q][2], bh[q][3], sbase + 16384 + off);
        }
#pragma unroll
        for (int mt = 0; mt < 4; mt++) {
#pragma unroll
            for (int nt = 0; nt < 8; nt++) {
                int q = nt >> 1, o = (nt & 1) * 2;
                mma16816(acc[mt][nt], ah[mt], bh[q][o], bh[q][o + 1]);
            }
        }
    }

    int gid = lane >> 2, tig = lane & 3;
    int nb = bn * 128 + wm * 64;
    int kb = bk * 128 + wn * 64;
#pragma unroll
    for (int nt = 0; nt < 8; nt++) {
        int c = kb + nt * 8 + tig * 2;
#pragma unroll
        for (int mt = 0; mt < 4; mt++) {
            int r0 = nb + mt * 16 + gid;
            int r1 = r0 + 8;
            float2 w0 = *reinterpret_cast<const float2*>(W + (size_t)r0 * 4096 + c);
            float2 w1 = *reinterpret_cast<const float2*>(W + (size_t)r1 * 4096 + c);
            __half2 h0 = __floats2half2_rn(w0.x + acc[mt][nt][0],
                                           w0.y + acc[mt][nt][1]);
            __half2 h1 = __floats2half2_rn(w1.x + acc[mt][nt][2],
                                           w1.y + acc[mt][nt][3]);
            *reinterpret_cast<__half2*>(g_Wh + (size_t)r0 * 4096 + c) = h0;
            *reinterpret_cast<__half2*>(g_Wh + (size_t)r1 * 4096 + c) = h1;
        }
    }
}

// ---------------------------------------------------------------------------
// Kernel 3: persistent GEMM  out = Xh * Wh^T + b  (fp16 in, fp32 acc).
// Grid = 304 persistent CTAs; each strides tiles blockIdx.x + i*304.
// One continuous chunk stream g (tile = g/64, kt = g%64, stage = g%3):
// the 3-stage TMA ring never drains at tile boundaries — next tile's first
// chunks load while this tile's epilogue runs.
// ---------------------------------------------------------------------------
__global__ void __launch_bounds__(128, 2)
gemm_kernel(const __grid_constant__ CUtensorMap mXh,
            const __grid_constant__ CUtensorMap mWh,
            const float* __restrict__ bias, float* __restrict__ out) {
    extern __shared__ char smem[];
    uint32_t sbase = (uint32_t)__cvta_generic_to_shared(smem);
    int tid = threadIdx.x;
    int lane = tid & 31, warp = tid >> 5;
    int wm = warp >> 1;
    int wn = warp & 1;

    uint32_t full[NSTAGES] = {sbase, sbase + 8, sbase + 16};

    if (tid == 0) {
        MBAR_INIT(full[0], 1);
        MBAR_INIT(full[1], 1);
        MBAR_INIT(full[2], 1);
    }
    __syncthreads();

    int nmine = (NTILES - blockIdx.x + gridDim.x - 1) / gridDim.x;
    int total = nmine * NCHUNK;

    // Issue chunk h of this CTA's global stream (h counts chunks across tiles).
    auto chunk_issue = [&](int h) {
        int t = blockIdx.x + (h >> 6) * gridDim.x;
        int tbn = t & 31, tbm = t >> 5;
        int kt = h & 63;
        int s = h % 3;
        uint32_t st = sbase + SMEM_DATA_OFF + s * SSTAGE;
        MBAR_EXPECT_TX(full[s], SSTAGE);
        tma2d(st,         &mXh, kt * BK, tbm * BM, full[s]);
        tma2d(st + 16384, &mWh, kt * BK, tbn * BN, full[s]);
    };

    if (tid == 0 && total > 0) {
        chunk_issue(0);
        if (total > 1) chunk_issue(1);
    }

    int arow = wm * 64 + (lane & 15);
    int nrow0 = wn * 64 + (lane & 7) + ((lane >> 4) << 3);

    uint32_t ah[2][4][4];
    uint32_t bh[2][4][4];
    int ph[NSTAGES] = {0, 0, 0};
    int g = 0;

    for (int idx = 0; idx < nmine; idx++) {
        int tile = blockIdx.x + idx * gridDim.x;
        int bn = tile & 31, bm = tile >> 5;

        float acc[4][8][4];
#pragma unroll
        for (int a = 0; a < 4; a++)
#pragma unroll
            for (int b = 0; b < 8; b++)
#pragma unroll
                for (int c = 0; c < 4; c++) acc[a][b][c] = 0.0f;

        for (int kt = 0; kt < NCHUNK; kt++, g++) {
            int cs = g % 3;
            // All warps finished reading stage (g+2)%3 at chunk g-1; safe to
            // refill it now.
            __syncthreads();
            if (tid == 0 && g + 2 < total) chunk_issue(g + 2);
            MBAR_WAIT(full[cs], ph[cs]);
            ph[cs] ^= 1;

            uint32_t st = sbase + SMEM_DATA_OFF + cs * SSTAGE;

            auto ldfrag = [&](int buf, int ks) {
                int ach = ks * 2 + (lane >> 4);
                int bch = ks * 2 + ((lane >> 3) & 1);
#pragma unroll
                for (int mt = 0; mt < 4; mt++) {
                    int row = arow + mt * 16;
                    uint32_t off = row * 128 + ((ach ^ (row & 7)) << 4);
                    ldsm4(ah[buf][mt][0], ah[buf][mt][1], ah[buf][mt][2],
                          ah[buf][mt][3], st + off);
                }
#pragma unroll
                for (int q = 0; q < 4; q++) {
                    int row = nrow0 + q * 16;
                    uint32_t off = row * 128 + ((bch ^ (row & 7)) << 4);
                    ldsm4(bh[buf][q][0], bh[buf][q][1], bh[buf][q][2],
                          bh[buf][q][3], st + 16384 + off);
                }
            };

            ldfrag(0, 0);
#pragma unroll
            for (int ks = 0; ks < 4; ks++) {
                int cur = ks & 1, nxt = cur ^ 1;
                if (ks < 3) ldfrag(nxt, ks + 1);
#pragma unroll
                for (int mt = 0; mt < 4; mt++) {
#pragma unroll
                    for (int nt = 0; nt < 8; nt++) {
                        int q = nt >> 1, o = (nt & 1) * 2;
                        mma16816(acc[mt][nt], ah[cur][mt], bh[cur][q][o],
                                 bh[cur][q][o + 1]);
                    }
                }
            }
        }

        // Epilogue for this tile (overlaps next tile's in-flight TMA loads).
        const float* bptr = bias + bn * BN + wn * 64;
        size_t outbase = (size_t)(bm * BM + wm * 64) * 4096 + bn * BN + wn * 64;
        int gid = lane >> 2, tig = lane & 3;
#pragma unroll
        for (int nt = 0; nt < 8; nt++) {
            int c = nt * 8 + tig * 2;
            float b0 = bptr[c], b1 = bptr[c + 1];
#pragma unroll
            for (int mt = 0; mt < 4; mt++) {
                int r = mt * 16 + gid;
                float2 v0 = make_float2(acc[mt][nt][0] + b0, acc[mt][nt][1] + b1);
                float2 v1 = make_float2(acc[mt][nt][2] + b0, acc[mt][nt][3] + b1);
                *reinterpret_cast<float2*>(out + outbase + (size_t)r * 4096 + c) = v0;
                *reinterpret_cast<float2*>(out + outbase + (size_t)(r + 8) * 4096 + c) = v1;
            }
        }
    }
}

// ---------------------------------------------------------------------------
typedef CUresult (*EncodeFn)(CUtensorMap*, CUtensorMapDataType, cuuint32_t, void*,
                             const cuuint64_t*, const cuuint64_t*, const cuuint32_t*,
                             const cuuint32_t*, CUtensorMapInterleave, CUtensorMapSwizzle,
                             CUtensorMapL2promotion, CUtensorMapFloatOOBfill);

static void make_map(EncodeFn enc, CUtensorMap* m, void* ptr, uint64_t rows) {
    cuuint64_t dims[2] = {(cuuint64_t)KTOT, (cuuint64_t)rows};
    cuuint64_t strides[1] = {(cuuint64_t)KTOT * 2};
    cuuint32_t box[2] = {BK, BM};
    cuuint32_t es[2] = {1, 1};
    enc(m, CU_TENSOR_MAP_DATA_TYPE_BFLOAT16, 2, ptr, dims, strides, box, es,
        CU_TENSOR_MAP_INTERLEAVE_NONE, CU_TENSOR_MAP_SWIZZLE_128B,
        CU_TENSOR_MAP_L2_PROMOTION_L2_128B, CU_TENSOR_MAP_FLOAT_OOB_FILL_NONE);
}

extern "C" void kernel_launch(void* const* d_in, const int* in_sizes, int n_in,
                              void* d_out, int out_size) {
    const float* x  = (const float*)d_in[0];
    const float* W  = (const float*)d_in[1];
    const float* b  = (const float*)d_in[2];
    const float* Au = (const float*)d_in[3];
    const float* Bu = (const float*)d_in[4];
    const float* A0 = (const float*)d_in[5];
    const float* B0 = (const float*)d_in[6];
    float* out = (float*)d_out;

    void* fp = nullptr;
    cudaDriverEntryPointQueryResult qr;
    cudaGetDriverEntryPoint("cuTensorMapEncodeTiled", &fp, cudaEnableDefault, &qr);
    EncodeFn enc = (EncodeFn)fp;

    void *pXh, *pWh;
    cudaGetSymbolAddress(&pXh, g_Xh);
    cudaGetSymbolAddress(&pWh, g_Wh);
    CUtensorMap mXh, mWh;
    make_map(enc, &mXh, pXh, MTOT);
    make_map(enc, &mWh, pWh, NTOT);

    int n4 = (MTOT * KTOT) / 4;
    split_x_kernel<<<(n4 / 2 + 255) / 256, 256>>>((const float4*)x, n4);
    pack_kernel<<<(KTOT * 64 + 255) / 256, 256>>>(Au, Bu, A0, B0);
    build_w_tc_kernel<<<dim3(KTOT / 128, NTOT / 128), 128>>>(W);

    int dsmem = SMEM_DATA_OFF + NSTAGES * SSTAGE;
    cudaFuncSetAttribute(gemm_kernel,
                         cudaFuncAttributeMaxDynamicSharedMemorySize, dsmem);
    gemm_kernel<<<GRID_PERSIST, 128, dsmem>>>(mXh, mWh, b, out);
}